// round 1
// baseline (speedup 1.0000x reference)
#include <cuda_runtime.h>

#define N_NODES 10000
#define N_EDGES 160000
#define C       16
#define C2      8
#define HID     64
#define NH      2
#define NG      16
#define F_IN    64
#define F_OUT   32

// ---------------- scratch (device globals; no allocations allowed) ----------
__device__ __align__(16) float g_x[N_NODES * C];
__device__ __align__(16) float g_q[NH * N_NODES * C];
__device__ __align__(16) float g_k[NH * N_NODES * C];
__device__ float    g_dist[N_EDGES];
__device__ float    g_logit[NH * N_EDGES];
__device__ unsigned g_m[NH * N_NODES];
__device__ float    g_z[NH * N_NODES];
__device__ __align__(16) float g_acc[NH * N_NODES * C];
__device__ float    g_pooled[NG * NH * C2];

// order-preserving float<->uint encoding for atomicMax on floats
__device__ __forceinline__ unsigned fenc(float f) {
    unsigned u = __float_as_uint(f);
    return (u & 0x80000000u) ? ~u : (u | 0x80000000u);
}
__device__ __forceinline__ float fdec(unsigned u) {
    return (u & 0x80000000u) ? __uint_as_float(u & 0x7fffffffu)
                             : __uint_as_float(~u);
}
#define ENC_NEG_INF 0x007FFFFFu   // fenc(-inf)

// ---------------- kernel 0: init scratch ------------------------------------
__global__ void k_init() {
    int i = blockIdx.x * blockDim.x + threadIdx.x;
    if (i < NH * N_NODES) { g_m[i] = ENC_NEG_INF; g_z[i] = 0.f; }
    if (i < NH * N_NODES * C) g_acc[i] = 0.f;
    if (i < NG * NH * C2) g_pooled[i] = 0.f;
}

// ---------------- kernel 1: node embed + q/k --------------------------------
__global__ void k_nodes(const float* __restrict__ NF,
                        const float* __restrict__ We,
                        const float* __restrict__ be,
                        const float* __restrict__ Wq,
                        const float* __restrict__ Wk) {
    __shared__ float sWe[F_IN * C];
    __shared__ float sbe[C];
    __shared__ float sWq[NH * C * C];
    __shared__ float sWk[NH * C * C];
    for (int i = threadIdx.x; i < F_IN * C; i += blockDim.x) sWe[i] = We[i];
    for (int i = threadIdx.x; i < C; i += blockDim.x) sbe[i] = be[i];
    for (int i = threadIdx.x; i < NH * C * C; i += blockDim.x) { sWq[i] = Wq[i]; sWk[i] = Wk[i]; }
    __syncthreads();

    int n = blockIdx.x * blockDim.x + threadIdx.x;
    if (n >= N_NODES) return;

    float x[C];
#pragma unroll
    for (int j = 0; j < C; j++) x[j] = sbe[j];
    const float* nf = NF + n * F_IN;
#pragma unroll 8
    for (int i = 0; i < F_IN; i++) {
        float v = nf[i];
#pragma unroll
        for (int j = 0; j < C; j++) x[j] = fmaf(v, sWe[i * C + j], x[j]);
    }
#pragma unroll
    for (int j = 0; j < C; j++) g_x[n * C + j] = x[j];

#pragma unroll
    for (int h = 0; h < NH; h++) {
        float q[C], k[C];
#pragma unroll
        for (int j = 0; j < C; j++) { q[j] = 0.f; k[j] = 0.f; }
#pragma unroll
        for (int i = 0; i < C; i++) {
            float xi = x[i];
#pragma unroll
            for (int j = 0; j < C; j++) {
                q[j] = fmaf(xi, sWq[h * C * C + i * C + j], q[j]);
                k[j] = fmaf(xi, sWk[h * C * C + i * C + j], k[j]);
            }
        }
        float* qp = g_q + (h * N_NODES + n) * C;
        float* kp = g_k + (h * N_NODES + n) * C;
#pragma unroll
        for (int j = 0; j < C; j++) { qp[j] = q[j]; kp[j] = k[j]; }
    }
}

// ---------------- kernel 2: edge logits + segment max -----------------------
__global__ void k_edge_logit(const float* __restrict__ pos,
                             const int* __restrict__ ei,
                             const float* __restrict__ W1,
                             const float* __restrict__ b1,
                             const float* __restrict__ Wa) {
    __shared__ float sW1[NH * HID], sb1[NH * HID], sWa[NH * HID];
    for (int i = threadIdx.x; i < NH * HID; i += blockDim.x) {
        sW1[i] = W1[i]; sb1[i] = b1[i]; sWa[i] = Wa[i];
    }
    __syncthreads();

    int e = blockIdx.x * blockDim.x + threadIdx.x;
    if (e >= N_EDGES) return;
    int s = ei[e];
    int t = ei[N_EDGES + e];

    float dx = pos[3 * t + 0] - pos[3 * s + 0];
    float dy = pos[3 * t + 1] - pos[3 * s + 1];
    float dz = pos[3 * t + 2] - pos[3 * s + 2];
    float d2 = dx * dx + dy * dy + dz * dz;
    float d  = sqrtf(d2);
    g_dist[e] = d;

#pragma unroll
    for (int h = 0; h < NH; h++) {
        float df = (h == 0) ? d : (1.0f / d2);
        float ab = 0.f;
#pragma unroll 16
        for (int j = 0; j < HID; j++) {
            float hj = fmaxf(fmaf(df, sW1[h * HID + j], sb1[h * HID + j]), 0.f);
            ab = fmaf(hj, sWa[h * HID + j], ab);
        }
        const float4* qt = (const float4*)(g_q + (h * N_NODES + t) * C);
        const float4* ks = (const float4*)(g_k + (h * N_NODES + s) * C);
        float dot = 0.f;
#pragma unroll
        for (int i4 = 0; i4 < 4; i4++) {
            float4 a = qt[i4], b = ks[i4];
            dot += a.x * b.x + a.y * b.y + a.z * b.z + a.w * b.w;
        }
        float lg = fmaf(dot, 0.25f, ab);   // 1/sqrt(C) = 0.25
        g_logit[h * N_EDGES + e] = lg;
        atomicMax(&g_m[h * N_NODES + t], fenc(lg));
    }
}

// ---------------- kernel 3: exp + weighted message accumulate ---------------
__global__ void k_edge_acc(const int* __restrict__ ei,
                           const float* __restrict__ W1,
                           const float* __restrict__ b1,
                           const float* __restrict__ Wv) {
    __shared__ float sW1[NH * HID], sb1[NH * HID];
    __shared__ __align__(16) float sWv0[NH * HID * C];   // [h][j][c], c-contiguous
    for (int i = threadIdx.x; i < NH * HID; i += blockDim.x) { sW1[i] = W1[i]; sb1[i] = b1[i]; }
    for (int i = threadIdx.x; i < NH * HID * C; i += blockDim.x) {
        int h = i / (HID * C);
        int r = i % (HID * C);
        int j = r / C;
        int c = r % C;
        sWv0[i] = Wv[(h * HID + j) * (C * 3) + 3 * c];   // column stride 3 -> slice m=0
    }
    __syncthreads();

    int e = blockIdx.x * blockDim.x + threadIdx.x;
    if (e >= N_EDGES) return;
    int s = ei[e];
    int t = ei[N_EDGES + e];

    float xs[C];
    {
        const float4* xp = (const float4*)(g_x + s * C);
#pragma unroll
        for (int i4 = 0; i4 < 4; i4++) {
            float4 v = xp[i4];
            xs[i4 * 4 + 0] = v.x; xs[i4 * 4 + 1] = v.y;
            xs[i4 * 4 + 2] = v.z; xs[i4 * 4 + 3] = v.w;
        }
    }
    float d = g_dist[e];
    float d2inv = 1.0f / (d * d);

#pragma unroll
    for (int h = 0; h < NH; h++) {
        float lg = g_logit[h * N_EDGES + e];
        float m  = fdec(g_m[h * N_NODES + t]);
        float ex = __expf(lg - m);
        atomicAdd(&g_z[h * N_NODES + t], ex);

        float df = (h == 0) ? d : d2inv;
        float wv0[C];
#pragma unroll
        for (int c = 0; c < C; c++) wv0[c] = 0.f;
#pragma unroll 8
        for (int j = 0; j < HID; j++) {
            float hj = fmaxf(fmaf(df, sW1[h * HID + j], sb1[h * HID + j]), 0.f);
            const float4* wp = (const float4*)(sWv0 + (h * HID + j) * C);
#pragma unroll
            for (int i4 = 0; i4 < 4; i4++) {
                float4 w = wp[i4];
                wv0[i4 * 4 + 0] = fmaf(hj, w.x, wv0[i4 * 4 + 0]);
                wv0[i4 * 4 + 1] = fmaf(hj, w.y, wv0[i4 * 4 + 1]);
                wv0[i4 * 4 + 2] = fmaf(hj, w.z, wv0[i4 * 4 + 2]);
                wv0[i4 * 4 + 3] = fmaf(hj, w.w, wv0[i4 * 4 + 3]);
            }
        }
        float* accp = g_acc + (h * N_NODES + t) * C;
#pragma unroll
        for (int c = 0; c < C; c++) {
            atomicAdd(&accp[c], ex * wv0[c] * xs[c]);
        }
    }
}

// ---------------- kernel 4: node output projection + batch pool -------------
__global__ void k_node_out(const int* __restrict__ batch,
                           const float* __restrict__ Wo) {
    __shared__ float sWo[NH * C * C2];      // Wo[h,0,c,j]
    __shared__ float sp[NG * NH * C2];
    for (int i = threadIdx.x; i < NH * C * C2; i += blockDim.x) {
        int h = i / (C * C2);
        int r = i % (C * C2);
        sWo[i] = Wo[h * 3 * C * C2 + r];    // li = 0 slice
    }
    for (int i = threadIdx.x; i < NG * NH * C2; i += blockDim.x) sp[i] = 0.f;
    __syncthreads();

    int n = blockIdx.x * blockDim.x + threadIdx.x;
    if (n < N_NODES) {
        int g = batch[n];
#pragma unroll
        for (int h = 0; h < NH; h++) {
            float z = g_z[h * N_NODES + n];
            if (z > 0.f) {
                float inv = 1.0f / z;
                float a[C];
                const float4* ap = (const float4*)(g_acc + (h * N_NODES + n) * C);
#pragma unroll
                for (int i4 = 0; i4 < 4; i4++) {
                    float4 v = ap[i4];
                    a[i4 * 4 + 0] = v.x; a[i4 * 4 + 1] = v.y;
                    a[i4 * 4 + 2] = v.z; a[i4 * 4 + 3] = v.w;
                }
#pragma unroll
                for (int j = 0; j < C2; j++) {
                    float o = 0.f;
#pragma unroll
                    for (int c = 0; c < C; c++)
                        o = fmaf(a[c], sWo[(h * C + c) * C2 + j], o);
                    atomicAdd(&sp[(g * NH + h) * C2 + j], o * inv);
                }
            }
        }
    }
    __syncthreads();
    for (int i = threadIdx.x; i < NG * NH * C2; i += blockDim.x) {
        float v = sp[i];
        if (v != 0.f) atomicAdd(&g_pooled[i], v);
    }
}

// ---------------- kernel 5: final projection --------------------------------
__global__ void k_final(const float* __restrict__ Wproj,
                        const float* __restrict__ bproj,
                        float* __restrict__ out) {
    int tid = threadIdx.x;
    if (tid >= NG * F_OUT) return;
    int g = tid / F_OUT;
    int o = tid % F_OUT;
    float acc = bproj[o];
#pragma unroll
    for (int t = 0; t < NH * C2; t++)
        acc = fmaf(g_pooled[g * (NH * C2) + t], Wproj[t * F_OUT + o], acc);
    out[g * F_OUT + o] = acc;
}

// ---------------- launch ----------------------------------------------------
extern "C" void kernel_launch(void* const* d_in, const int* in_sizes, int n_in,
                              void* d_out, int out_size) {
    const float* NF    = (const float*)d_in[0];
    const float* pos   = (const float*)d_in[1];
    const float* We    = (const float*)d_in[2];
    const float* be    = (const float*)d_in[3];
    const float* Wq    = (const float*)d_in[4];
    const float* Wk    = (const float*)d_in[5];
    const float* W1    = (const float*)d_in[6];
    const float* b1    = (const float*)d_in[7];
    const float* Wa    = (const float*)d_in[8];
    const float* Wv    = (const float*)d_in[9];
    const float* Wo    = (const float*)d_in[10];
    const float* Wproj = (const float*)d_in[11];
    const float* bproj = (const float*)d_in[12];
    const int*   ei    = (const int*)d_in[13];
    const int*   batch = (const int*)d_in[14];
    float* out = (float*)d_out;

    k_init<<<(NH * N_NODES * C + 255) / 256, 256>>>();
    k_nodes<<<(N_NODES + 255) / 256, 256>>>(NF, We, be, Wq, Wk);
    k_edge_logit<<<(N_EDGES + 255) / 256, 256>>>(pos, ei, W1, b1, Wa);
    k_edge_acc<<<(N_EDGES + 255) / 256, 256>>>(ei, W1, b1, Wv);
    k_node_out<<<(N_NODES + 255) / 256, 256>>>(batch, Wo);
    k_final<<<1, 512>>>(Wproj, bproj, out);
}

// round 2
// speedup vs baseline: 1.3920x; 1.3920x over previous
#include <cuda_runtime.h>

#define N_NODES 10000
#define N_EDGES 160000
#define C       16
#define C2      8
#define HID     64
#define NH      2
#define NG      16
#define F_IN    64
#define F_OUT   32
#define NI      65   // intervals = HID+1

// ---------------- scratch (device globals; no allocations allowed) ----------
__device__ __align__(16) float g_x[N_NODES * C];                 // [n][c]
__device__ __align__(16) float g_q[N_NODES * NH * C];            // [n][h][c]
__device__ __align__(16) float g_k[N_NODES * NH * C];            // [n][h][c]
__device__ float    g_dist[N_EDGES];
__device__ __align__(8) float g_logit[N_EDGES * NH];             // [e][h]
__device__ __align__(8) unsigned g_m[N_NODES * NH];              // [n][h]
__device__ float    g_z[N_NODES * NH];                           // [n][h]
__device__ __align__(16) float g_acc[N_NODES * NH * C];          // [n][h][c]
__device__ float    g_pooled[NG * NH * C2];

// piecewise-linear tables:  wv0[c](df) = S0[c] + df*S1[c];  bias(df) = A0 + df*A1
__device__ float g_t [NH][HID];      // sorted breakpoints
__device__ __align__(16) float g_S0[NH][NI][C];
__device__ __align__(16) float g_S1[NH][NI][C];
__device__ float g_A0[NH][NI];
__device__ float g_A1[NH][NI];

// order-preserving float<->uint encoding for atomicMax on floats
__device__ __forceinline__ unsigned fenc(float f) {
    unsigned u = __float_as_uint(f);
    return (u & 0x80000000u) ? ~u : (u | 0x80000000u);
}
__device__ __forceinline__ float fdec(unsigned u) {
    return (u & 0x80000000u) ? __uint_as_float(u & 0x7fffffffu)
                             : __uint_as_float(~u);
}
#define ENC_NEG_INF 0x007FFFFFu   // fenc(-inf)

__device__ __forceinline__ void red_v4(float* p, float4 v) {
    asm volatile("red.global.add.v4.f32 [%0], {%1, %2, %3, %4};"
                 :: "l"(p), "f"(v.x), "f"(v.y), "f"(v.z), "f"(v.w) : "memory");
}

// binary search: number of sorted breakpoints strictly < df  (result in [0,64])
__device__ __forceinline__ int bsearch64(const float* t, float df) {
    int lo = 0, hi = HID;
    while (lo < hi) {
        int mid = (lo + hi) >> 1;
        if (t[mid] < df) lo = mid + 1; else hi = mid;
    }
    return lo;
}

// ---------------- kernel 0: init scratch ------------------------------------
__global__ void k_init() {
    int i = blockIdx.x * blockDim.x + threadIdx.x;
    if (i < NH * N_NODES) { g_m[i] = ENC_NEG_INF; g_z[i] = 0.f; }
    if (i < NH * N_NODES * C) g_acc[i] = 0.f;
    if (i < NG * NH * C2) g_pooled[i] = 0.f;
}

// ---------------- kernel T: build piecewise-linear tables -------------------
__global__ void k_table(const float* __restrict__ W1,
                        const float* __restrict__ b1,
                        const float* __restrict__ Wa,
                        const float* __restrict__ Wv) {
    __shared__ float st[NH][HID];
    int tid = threadIdx.x;
    if (tid < NH) {
        float tl[HID];
        for (int j = 0; j < HID; j++) {
            float w = W1[tid * HID + j], b = b1[tid * HID + j];
            tl[j] = (w != 0.f) ? (-b / w) : -1e30f;   // w==0: const term, park at -inf
        }
        // insertion sort (64 elems, one thread, once per launch)
        for (int i = 1; i < HID; i++) {
            float key = tl[i]; int j = i - 1;
            while (j >= 0 && tl[j] > key) { tl[j + 1] = tl[j]; j--; }
            tl[j + 1] = key;
        }
        for (int j = 0; j < HID; j++) { st[tid][j] = tl[j]; g_t[tid][j] = tl[j]; }
    }
    __syncthreads();
    if (tid < NH * NI) {
        int h = tid / NI, i = tid % NI;
        float lo = (i == 0)   ? st[h][0] - 1.0f      : st[h][i - 1];
        float hi = (i == HID) ? st[h][HID - 1] + 1.0f : st[h][i];
        float mid = 0.5f * (lo + hi);
        float S0[C], S1[C], A0 = 0.f, A1 = 0.f;
#pragma unroll
        for (int c = 0; c < C; c++) { S0[c] = 0.f; S1[c] = 0.f; }
        for (int j = 0; j < HID; j++) {
            float w = W1[h * HID + j], b = b1[h * HID + j];
            if (fmaf(w, mid, b) > 0.f) {
                float wa = Wa[h * HID + j];
                A0 = fmaf(b, wa, A0);
                A1 = fmaf(w, wa, A1);
#pragma unroll
                for (int c = 0; c < C; c++) {
                    float wv = Wv[(h * HID + j) * (C * 3) + 3 * c]; // m=0 slice
                    S0[c] = fmaf(b, wv, S0[c]);
                    S1[c] = fmaf(w, wv, S1[c]);
                }
            }
        }
#pragma unroll
        for (int c = 0; c < C; c++) { g_S0[h][i][c] = S0[c]; g_S1[h][i][c] = S1[c]; }
        g_A0[h][i] = A0; g_A1[h][i] = A1;
    }
}

// ---------------- kernel 1: node embed + q/k (interleaved head layout) ------
__global__ void k_nodes(const float* __restrict__ NF,
                        const float* __restrict__ We,
                        const float* __restrict__ be,
                        const float* __restrict__ Wq,
                        const float* __restrict__ Wk) {
    __shared__ float sWe[F_IN * C];
    __shared__ float sbe[C];
    __shared__ float sWq[NH * C * C];
    __shared__ float sWk[NH * C * C];
    for (int i = threadIdx.x; i < F_IN * C; i += blockDim.x) sWe[i] = We[i];
    for (int i = threadIdx.x; i < C; i += blockDim.x) sbe[i] = be[i];
    for (int i = threadIdx.x; i < NH * C * C; i += blockDim.x) { sWq[i] = Wq[i]; sWk[i] = Wk[i]; }
    __syncthreads();

    int n = blockIdx.x * blockDim.x + threadIdx.x;
    if (n >= N_NODES) return;

    float x[C];
#pragma unroll
    for (int j = 0; j < C; j++) x[j] = sbe[j];
    const float* nf = NF + n * F_IN;
#pragma unroll 8
    for (int i = 0; i < F_IN; i++) {
        float v = nf[i];
#pragma unroll
        for (int j = 0; j < C; j++) x[j] = fmaf(v, sWe[i * C + j], x[j]);
    }
#pragma unroll
    for (int j = 0; j < C; j++) g_x[n * C + j] = x[j];

#pragma unroll
    for (int h = 0; h < NH; h++) {
        float q[C], k[C];
#pragma unroll
        for (int j = 0; j < C; j++) { q[j] = 0.f; k[j] = 0.f; }
#pragma unroll
        for (int i = 0; i < C; i++) {
            float xi = x[i];
#pragma unroll
            for (int j = 0; j < C; j++) {
                q[j] = fmaf(xi, sWq[h * C * C + i * C + j], q[j]);
                k[j] = fmaf(xi, sWk[h * C * C + i * C + j], k[j]);
            }
        }
        float* qp = g_q + (n * NH + h) * C;
        float* kp = g_k + (n * NH + h) * C;
#pragma unroll
        for (int j = 0; j < C; j++) { qp[j] = q[j]; kp[j] = k[j]; }
    }
}

// ---------------- kernel 2: edge logits + segment max (table-based) ---------
__global__ void k_edge_logit(const float* __restrict__ pos,
                             const int* __restrict__ ei) {
    __shared__ float st[NH][HID];
    __shared__ float sA0[NH][NI];
    __shared__ float sA1[NH][NI];
    for (int i = threadIdx.x; i < NH * HID; i += blockDim.x)
        st[i / HID][i % HID] = g_t[i / HID][i % HID];
    for (int i = threadIdx.x; i < NH * NI; i += blockDim.x) {
        sA0[i / NI][i % NI] = g_A0[i / NI][i % NI];
        sA1[i / NI][i % NI] = g_A1[i / NI][i % NI];
    }
    __syncthreads();

    int e = blockIdx.x * blockDim.x + threadIdx.x;
    if (e >= N_EDGES) return;
    int s = ei[e];
    int t = ei[N_EDGES + e];

    float dx = pos[3 * t + 0] - pos[3 * s + 0];
    float dy = pos[3 * t + 1] - pos[3 * s + 1];
    float dz = pos[3 * t + 2] - pos[3 * s + 2];
    float d2 = dx * dx + dy * dy + dz * dz;
    float d  = sqrtf(d2);
    g_dist[e] = d;
    float df_h[NH] = { d, 1.0f / d2 };

    float2 lg2;
#pragma unroll
    for (int h = 0; h < NH; h++) {
        float df = df_h[h];
        int idx = bsearch64(st[h], df);
        float ab = fmaf(df, sA1[h][idx], sA0[h][idx]);

        const float4* qt = (const float4*)(g_q + (t * NH + h) * C);
        const float4* ks = (const float4*)(g_k + (s * NH + h) * C);
        float dot = 0.f;
#pragma unroll
        for (int i4 = 0; i4 < 4; i4++) {
            float4 a = qt[i4], b = ks[i4];
            dot += a.x * b.x + a.y * b.y + a.z * b.z + a.w * b.w;
        }
        float lg = fmaf(dot, 0.25f, ab);   // 1/sqrt(C) = 0.25
        (h == 0 ? lg2.x : lg2.y) = lg;
        atomicMax(&g_m[t * NH + h], fenc(lg));
    }
    *(float2*)(g_logit + e * NH) = lg2;
}

// ---------------- kernel 3: exp + weighted message accumulate (table) -------
__global__ void k_edge_acc(const int* __restrict__ ei) {
    __shared__ float st[NH][HID];
    __shared__ __align__(16) float sS0[NH][NI][C];
    __shared__ __align__(16) float sS1[NH][NI][C];
    for (int i = threadIdx.x; i < NH * HID; i += blockDim.x)
        st[i / HID][i % HID] = g_t[i / HID][i % HID];
    for (int i = threadIdx.x; i < NH * NI * (C / 4); i += blockDim.x) {
        ((float4*)sS0)[i] = ((const float4*)g_S0)[i];
        ((float4*)sS1)[i] = ((const float4*)g_S1)[i];
    }
    __syncthreads();

    int e = blockIdx.x * blockDim.x + threadIdx.x;
    if (e >= N_EDGES) return;
    int s = ei[e];
    int t = ei[N_EDGES + e];

    float4 xs[4];
    {
        const float4* xp = (const float4*)(g_x + s * C);
#pragma unroll
        for (int i4 = 0; i4 < 4; i4++) xs[i4] = xp[i4];
    }
    float d = g_dist[e];
    float df_h[NH] = { d, 1.0f / (d * d) };

    float2 lg2 = *(const float2*)(g_logit + e * NH);
    uint2  m2  = *(const uint2*)(g_m + t * NH);
    float lg_h[NH] = { lg2.x, lg2.y };
    float m_h [NH] = { fdec(m2.x), fdec(m2.y) };

#pragma unroll
    for (int h = 0; h < NH; h++) {
        float ex = __expf(lg_h[h] - m_h[h]);
        atomicAdd(&g_z[t * NH + h], ex);

        float df = df_h[h];
        int idx = bsearch64(st[h], df);
        const float4* p0 = (const float4*)sS0[h][idx];
        const float4* p1 = (const float4*)sS1[h][idx];
        float* accp = g_acc + (t * NH + h) * C;
#pragma unroll
        for (int i4 = 0; i4 < 4; i4++) {
            float4 a = p0[i4], b = p1[i4], xv = xs[i4];
            float4 msg;
            msg.x = ex * fmaf(df, b.x, a.x) * xv.x;
            msg.y = ex * fmaf(df, b.y, a.y) * xv.y;
            msg.z = ex * fmaf(df, b.z, a.z) * xv.z;
            msg.w = ex * fmaf(df, b.w, a.w) * xv.w;
            red_v4(accp + i4 * 4, msg);
        }
    }
}

// ---------------- kernel 4: node output projection + batch pool -------------
__global__ void k_node_out(const int* __restrict__ batch,
                           const float* __restrict__ Wo) {
    __shared__ float sWo[NH * C * C2];      // Wo[h,0,c,j]
    __shared__ float sp[NG * NH * C2];
    for (int i = threadIdx.x; i < NH * C * C2; i += blockDim.x) {
        int h = i / (C * C2);
        int r = i % (C * C2);
        sWo[i] = Wo[h * 3 * C * C2 + r];    // li = 0 slice
    }
    for (int i = threadIdx.x; i < NG * NH * C2; i += blockDim.x) sp[i] = 0.f;
    __syncthreads();

    int n = blockIdx.x * blockDim.x + threadIdx.x;
    if (n < N_NODES) {
        int g = batch[n];
#pragma unroll
        for (int h = 0; h < NH; h++) {
            float z = g_z[n * NH + h];
            if (z > 0.f) {
                float inv = 1.0f / z;
                float a[C];
                const float4* ap = (const float4*)(g_acc + (n * NH + h) * C);
#pragma unroll
                for (int i4 = 0; i4 < 4; i4++) {
                    float4 v = ap[i4];
                    a[i4 * 4 + 0] = v.x; a[i4 * 4 + 1] = v.y;
                    a[i4 * 4 + 2] = v.z; a[i4 * 4 + 3] = v.w;
                }
#pragma unroll
                for (int j = 0; j < C2; j++) {
                    float o = 0.f;
#pragma unroll
                    for (int c = 0; c < C; c++)
                        o = fmaf(a[c], sWo[(h * C + c) * C2 + j], o);
                    atomicAdd(&sp[(g * NH + h) * C2 + j], o * inv);
                }
            }
        }
    }
    __syncthreads();
    for (int i = threadIdx.x; i < NG * NH * C2; i += blockDim.x) {
        float v = sp[i];
        if (v != 0.f) atomicAdd(&g_pooled[i], v);
    }
}

// ---------------- kernel 5: final projection --------------------------------
__global__ void k_final(const float* __restrict__ Wproj,
                        const float* __restrict__ bproj,
                        float* __restrict__ out) {
    int tid = threadIdx.x;
    if (tid >= NG * F_OUT) return;
    int g = tid / F_OUT;
    int o = tid % F_OUT;
    float acc = bproj[o];
#pragma unroll
    for (int t = 0; t < NH * C2; t++)
        acc = fmaf(g_pooled[g * (NH * C2) + t], Wproj[t * F_OUT + o], acc);
    out[g * F_OUT + o] = acc;
}

// ---------------- launch ----------------------------------------------------
extern "C" void kernel_launch(void* const* d_in, const int* in_sizes, int n_in,
                              void* d_out, int out_size) {
    const float* NF    = (const float*)d_in[0];
    const float* pos   = (const float*)d_in[1];
    const float* We    = (const float*)d_in[2];
    const float* be    = (const float*)d_in[3];
    const float* Wq    = (const float*)d_in[4];
    const float* Wk    = (const float*)d_in[5];
    const float* W1    = (const float*)d_in[6];
    const float* b1    = (const float*)d_in[7];
    const float* Wa    = (const float*)d_in[8];
    const float* Wv    = (const float*)d_in[9];
    const float* Wo    = (const float*)d_in[10];
    const float* Wproj = (const float*)d_in[11];
    const float* bproj = (const float*)d_in[12];
    const int*   ei    = (const int*)d_in[13];
    const int*   batch = (const int*)d_in[14];
    float* out = (float*)d_out;

    k_init<<<(NH * N_NODES * C + 255) / 256, 256>>>();
    k_table<<<1, 256>>>(W1, b1, Wa, Wv);
    k_nodes<<<(N_NODES + 255) / 256, 256>>>(NF, We, be, Wq, Wk);
    k_edge_logit<<<(N_EDGES + 255) / 256, 256>>>(pos, ei);
    k_edge_acc<<<(N_EDGES + 255) / 256, 256>>>(ei);
    k_node_out<<<(N_NODES + 255) / 256, 256>>>(batch, Wo);
    k_final<<<1, 512>>>(Wproj, bproj, out);
}